// round 6
// baseline (speedup 1.0000x reference)
#include <cuda_runtime.h>
#include <cstdint>

#define TPB   128     // 4 warps per block
#define NW    4       // warps per block
#define TILE_F4 128   // 32 rows x 4 float4 per warp-tile (2 KB)

// ---------------------------------------------------------------------------
// BinaryTreeRNN: out[i] = tree_combine( x[i,0:16] @ W_leaf^T + b_leaf )
// Params in __constant__ (LDC/LDCU port, zero L1TEX phases).
// x staged via WARP-LOCAL double-buffered cp.async (LDGSTS -> smem, no
// prefetch registers, no block barriers): tile j+1 streams in while tile j
// computes. Warps drift independently -> DRAM stays fed.
// ---------------------------------------------------------------------------

struct __align__(16) CParams {
    float2 Wp[4][16];   // [pair p][k] = (W[2p][k], W[2p+1][k])
    float2 bp[4];       // (b_leaf[2p], b_leaf[2p+1])
    float4 node[7];     // (A, M, C, b): val = A*s + M*l*r + C*sin(s) + b
};

__constant__ CParams cP;
__device__ CParams gStage;

__global__ void setup_kernel(const float* __restrict__ W,
                             const float* __restrict__ bl,
                             const float* __restrict__ w0,
                             const float* __restrict__ w1,
                             const float* __restrict__ w2,
                             const float* __restrict__ b0,
                             const float* __restrict__ b1,
                             const float* __restrict__ b2,
                             const float* __restrict__ om0,
                             const float* __restrict__ om1,
                             const float* __restrict__ om2)
{
    int t = threadIdx.x;
    if (t < 64) {
        int p = t >> 4, k = t & 15;
        gStage.Wp[p][k] = make_float2(W[(2 * p) * 16 + k], W[(2 * p + 1) * 16 + k]);
    } else if (t < 68) {
        int p = t - 64;
        gStage.bp[p] = make_float2(bl[2 * p], bl[2 * p + 1]);
    } else if (t < 75) {
        int i = t - 68;   // 0-3: level2, 4-5: level1, 6: level0
        const float* om;
        float w, b;
        if (i < 4)      { om = om2 + 4 * i;       w = w2[i];     b = b2[i]; }
        else if (i < 6) { om = om1 + 4 * (i - 4); w = w1[i - 4]; b = b1[i - 4]; }
        else            { om = om0;               w = w0[0];     b = b0[0]; }
        float e0 = expf(om[0]);
        float e1 = expf(om[1]);
        float e2 = expf(om[2]);
        float e3 = expf(om[3]);
        float inv = w / (e0 + e1 + e2 + e3);   // fold w into softmax coeffs
        gStage.node[i] = make_float4((e0 + e3) * inv, e1 * inv, e2 * inv, b);
    }
}

// ---- packed fp32x2 + async helpers (sm_103a) -------------------------------

__device__ __forceinline__ unsigned long long fma2(unsigned long long a,
                                                   unsigned long long b,
                                                   unsigned long long c)
{
    unsigned long long d;
    asm("fma.rn.f32x2 %0, %1, %2, %3;" : "=l"(d) : "l"(a), "l"(b), "l"(c));
    return d;
}

__device__ __forceinline__ unsigned long long dup2(float v)
{
    unsigned long long d;
    asm("mov.b64 %0, {%1, %1};" : "=l"(d) : "f"(v));
    return d;
}

__device__ __forceinline__ void unpack2(unsigned long long v, float& lo, float& hi)
{
    asm("mov.b64 {%0, %1}, %2;" : "=f"(lo), "=f"(hi) : "l"(v));
}

__device__ __forceinline__ void cp16(uint32_t smem_dst, const void* gsrc)
{
    asm volatile("cp.async.cg.shared.global [%0], [%1], 16;\n"
                 :: "r"(smem_dst), "l"(gsrc) : "memory");
}

__device__ __forceinline__ void cp_commit()
{
    asm volatile("cp.async.commit_group;\n" ::: "memory");
}

template <int N>
__device__ __forceinline__ void cp_wait()
{
    asm volatile("cp.async.wait_group %0;\n" :: "n"(N) : "memory");
}

// ---- main kernel -----------------------------------------------------------

__global__ void __launch_bounds__(TPB, 12)
tree_rnn_kernel(const float4* __restrict__ x4, float* __restrict__ out, int n)
{
    __shared__ float4 buf[NW][2][TILE_F4];   // per-warp double buffer (2x2KB)
    const int lane = threadIdx.x & 31;
    const int warp = threadIdx.x >> 5;

    const int nwarps = gridDim.x * NW;
    const int ntiles = (n + 31) >> 5;
    const int n4 = n * 4;

    const uint32_t sbase =
        (uint32_t)__cvta_generic_to_shared(&buf[warp][0][0]);

    // issue cp.async for tile ti into buffer b (XOR-swizzled destinations)
    auto issue = [&](int ti, int b) {
        int base4 = ti * TILE_F4;
#pragma unroll
        for (int m = 0; m < 4; m++) {
            int li = m * 32 + lane;
            int g4 = base4 + li;
            int r = li >> 2, q = li & 3;
            uint32_t dst = sbase + (uint32_t)(b * (TILE_F4 * 16)
                          + (((r << 2) + (q ^ ((r >> 1) & 3))) << 4));
            if (g4 < n4) cp16(dst, x4 + g4);
        }
        cp_commit();
    };

    int tl = blockIdx.x * NW + warp;
    if (tl < ntiles) issue(tl, 0);
    int cur = 0;

    while (tl < ntiles) {
        const int nxt = tl + nwarps;
        if (nxt < ntiles) issue(nxt, cur ^ 1);
        else              cp_commit();     // empty group keeps counts aligned
        cp_wait<1>();                      // tile tl landed; nxt still in flight
        __syncwarp();

        const int row = tl * 32 + lane;
        if (row < n) {
            const float4* tb = buf[warp][cur];
            const int swz = (lane >> 1) & 3;

            // leaf matvec, chunked: one LDS.128 of x per 4 k-values
            unsigned long long acc0 =
                *reinterpret_cast<const unsigned long long*>(&cP.bp[0]);
            unsigned long long acc1 =
                *reinterpret_cast<const unsigned long long*>(&cP.bp[1]);
            unsigned long long acc2 =
                *reinterpret_cast<const unsigned long long*>(&cP.bp[2]);
            unsigned long long acc3 =
                *reinterpret_cast<const unsigned long long*>(&cP.bp[3]);
#pragma unroll
            for (int c = 0; c < 4; c++) {
                float4 xv = tb[(lane << 2) + (c ^ swz)];
                unsigned long long x0 = dup2(xv.x);
                unsigned long long x1 = dup2(xv.y);
                unsigned long long x2 = dup2(xv.z);
                unsigned long long x3 = dup2(xv.w);
#pragma unroll
                for (int p = 0; p < 4; p++) {
                    const float2* wr = &cP.Wp[p][4 * c];
                    ulonglong2 wa = *reinterpret_cast<const ulonglong2*>(wr);
                    unsigned long long a =
                        (p == 0) ? acc0 : (p == 1) ? acc1 : (p == 2) ? acc2 : acc3;
                    a = fma2(wa.x, x0, a);
                    a = fma2(wa.y, x1, a);
                    ulonglong2 wb = *reinterpret_cast<const ulonglong2*>(wr + 2);
                    a = fma2(wb.x, x2, a);
                    a = fma2(wb.y, x3, a);
                    if (p == 0) acc0 = a; else if (p == 1) acc1 = a;
                    else if (p == 2) acc2 = a; else acc3 = a;
                }
            }
            float h[8];
            unpack2(acc0, h[0], h[1]);
            unpack2(acc1, h[2], h[3]);
            unpack2(acc2, h[4], h[5]);
            unpack2(acc3, h[6], h[7]);

            // tree combine: val = A*s + M*(l*r) + C*sin(s) + b
            float g[4];
#pragma unroll
            for (int k = 0; k < 4; k++) {
                float4 np = cP.node[k];
                float l = h[2 * k], r = h[2 * k + 1];
                float s = l + r;
                g[k] = fmaf(np.x, s, fmaf(np.y, l * r, fmaf(np.z, __sinf(s), np.w)));
            }
            float u[2];
#pragma unroll
            for (int k = 0; k < 2; k++) {
                float4 np = cP.node[4 + k];
                float l = g[2 * k], r = g[2 * k + 1];
                float s = l + r;
                u[k] = fmaf(np.x, s, fmaf(np.y, l * r, fmaf(np.z, __sinf(s), np.w)));
            }
            {
                float4 np = cP.node[6];
                float l = u[0], r = u[1];
                float s = l + r;
                out[row] = fmaf(np.x, s, fmaf(np.y, l * r, fmaf(np.z, __sinf(s), np.w)));
            }
        }
        __syncwarp();   // all lanes done reading buf[cur] before it is reused
        tl = nxt;
        cur ^= 1;
    }
}

extern "C" void kernel_launch(void* const* d_in, const int* in_sizes, int n_in,
                              void* d_out, int out_size)
{
    const float* x      = (const float*)d_in[0];
    const float* W_leaf = (const float*)d_in[1];
    const float* b_leaf = (const float*)d_in[2];
    const float* w0     = (const float*)d_in[3];
    const float* w1     = (const float*)d_in[4];
    const float* w2     = (const float*)d_in[5];
    const float* b0     = (const float*)d_in[6];
    const float* b1     = (const float*)d_in[7];
    const float* b2     = (const float*)d_in[8];
    const float* om0    = (const float*)d_in[9];
    const float* om1    = (const float*)d_in[10];
    const float* om2    = (const float*)d_in[11];

    int n = in_sizes[0] / 16;

    setup_kernel<<<1, 128>>>(W_leaf, b_leaf, w0, w1, w2, b0, b1, b2,
                             om0, om1, om2);
    void* stage_ptr = nullptr;
    cudaGetSymbolAddress(&stage_ptr, gStage);
    cudaMemcpyToSymbolAsync(cP, stage_ptr, sizeof(CParams), 0,
                            cudaMemcpyDeviceToDevice);

    int ntiles = (n + 31) / 32;
    int max_blocks = (ntiles + NW - 1) / NW;
    int blocks = 148 * 12;                 // single persistent-ish wave
    if (blocks > max_blocks) blocks = max_blocks;
    if (blocks < 1) blocks = 1;

    tree_rnn_kernel<<<blocks, TPB>>>(
        reinterpret_cast<const float4*>(x), (float*)d_out, n);
}

// round 7
// speedup vs baseline: 1.0010x; 1.0010x over previous
#include <cuda_runtime.h>
#include <cstdint>

#define BLOCK 256

// ---------------------------------------------------------------------------
// BinaryTreeRNN: out[i] = tree_combine( x[i,0:16] @ W_leaf^T + b_leaf )
// 2 graph nodes only:
//   (1) D2D memcpy of raw W_leaf into __constant__ (natural layout -- the
//       matvec packs accumulators over (even k, odd k), so no interleave and
//       no setup kernel is needed).
//   (2) main kernel: per-block fold of the tiny params into shared, swizzled
//       smem transpose of x, fp32x2 matvec with W on the constant port.
// ---------------------------------------------------------------------------

__constant__ __align__(16) float cW[128];   // W_leaf, raw row-major [8][16]

// ---- packed fp32x2 helpers (sm_103a) --------------------------------------

__device__ __forceinline__ unsigned long long fma2(unsigned long long a,
                                                   unsigned long long b,
                                                   unsigned long long c)
{
    unsigned long long d;
    asm("fma.rn.f32x2 %0, %1, %2, %3;" : "=l"(d) : "l"(a), "l"(b), "l"(c));
    return d;
}

__device__ __forceinline__ void unpack2(unsigned long long v, float& lo, float& hi)
{
    asm("mov.b64 {%0, %1}, %2;" : "=f"(lo), "=f"(hi) : "l"(v));
}

// ---- main kernel -----------------------------------------------------------

__global__ void __launch_bounds__(BLOCK)
tree_rnn_kernel(const float4* __restrict__ x4, float* __restrict__ out, int n,
                const float* __restrict__ bl,
                const float* __restrict__ w0,
                const float* __restrict__ w1,
                const float* __restrict__ w2,
                const float* __restrict__ b0,
                const float* __restrict__ b1,
                const float* __restrict__ b2,
                const float* __restrict__ om0,
                const float* __restrict__ om1,
                const float* __restrict__ om2)
{
    __shared__ float4 tile[BLOCK * 4];   // 256 rows x 16 floats, XOR-swizzled
    __shared__ float4 snode[7];          // (A, M, C, b) per tree node
    __shared__ float4 sbias[2];          // b_leaf as 2 float4

    const int t = threadIdx.x;

    // ---- Phase A: fold tiny params into shared (tiny, L2-hot reads) -------
    if (t < 7) {
        int i = t;   // 0-3: level2, 4-5: level1, 6: level0
        const float* om;
        float w, b;
        if (i < 4)      { om = om2 + 4 * i;       w = w2[i];     b = b2[i]; }
        else if (i < 6) { om = om1 + 4 * (i - 4); w = w1[i - 4]; b = b1[i - 4]; }
        else            { om = om0;               w = w0[0];     b = b0[0]; }
        float e0 = expf(om[0]);
        float e1 = expf(om[1]);
        float e2 = expf(om[2]);
        float e3 = expf(om[3]);
        float inv = w / (e0 + e1 + e2 + e3);   // fold w into softmax coeffs
        snode[i] = make_float4((e0 + e3) * inv, e1 * inv, e2 * inv, b);
    } else if (t < 9) {
        sbias[t - 7] = reinterpret_cast<const float4*>(bl)[t - 7];
    }

    // ---- Phase B: coalesced tile load, XOR-swizzled store ------------------
    const int n4 = n * 4;
    const int base4 = blockIdx.x * (BLOCK * 4);
#pragma unroll
    for (int j = 0; j < 4; j++) {
        int li = j * BLOCK + t;
        int g4 = base4 + li;
        float4 v;
        if (g4 < n4) v = x4[g4];
        else         v = make_float4(0.f, 0.f, 0.f, 0.f);
        int r = li >> 2;
        int q = li & 3;
        tile[(r << 2) + (q ^ ((r >> 1) & 3))] = v;
    }
    __syncthreads();

    const int row = blockIdx.x * BLOCK + t;
    if (row >= n) return;

    // gather own row as x-pairs: float4 slot == ulonglong2{(x0,x1),(x2,x3)}
    const ulonglong2* tb = reinterpret_cast<const ulonglong2*>(tile);
    const int swz = (t >> 1) & 3;
    ulonglong2 xq0 = tb[(t << 2) + (0 ^ swz)];
    ulonglong2 xq1 = tb[(t << 2) + (1 ^ swz)];
    ulonglong2 xq2 = tb[(t << 2) + (2 ^ swz)];
    ulonglong2 xq3 = tb[(t << 2) + (3 ^ swz)];

    float4 bia0 = sbias[0];
    float4 bia1 = sbias[1];
    const float bj[8] = { bia0.x, bia0.y, bia0.z, bia0.w,
                          bia1.x, bia1.y, bia1.z, bia1.w };

    // leaf matvec: acc2[j] = ((even-k partial), (odd-k partial)), W from the
    // constant port in its natural layout (cw[j*4+c] = W[j][4c..4c+3]).
    const ulonglong2* cw = reinterpret_cast<const ulonglong2*>(cW);
    float h[8];
#pragma unroll
    for (int j = 0; j < 8; j++) {
        unsigned long long acc = 0ULL;   // (0.0f, 0.0f)
        ulonglong2 w0q = cw[j * 4 + 0];
        acc = fma2(w0q.x, xq0.x, acc);
        acc = fma2(w0q.y, xq0.y, acc);
        ulonglong2 w1q = cw[j * 4 + 1];
        acc = fma2(w1q.x, xq1.x, acc);
        acc = fma2(w1q.y, xq1.y, acc);
        ulonglong2 w2q = cw[j * 4 + 2];
        acc = fma2(w2q.x, xq2.x, acc);
        acc = fma2(w2q.y, xq2.y, acc);
        ulonglong2 w3q = cw[j * 4 + 3];
        acc = fma2(w3q.x, xq3.x, acc);
        acc = fma2(w3q.y, xq3.y, acc);
        float lo, hi;
        unpack2(acc, lo, hi);
        h[j] = lo + hi + bj[j];
    }

    // tree combine: val = A*s + M*(l*r) + C*sin(s) + b
    float g[4];
#pragma unroll
    for (int k = 0; k < 4; k++) {
        float4 np = snode[k];
        float l = h[2 * k], r = h[2 * k + 1];
        float s = l + r;
        g[k] = fmaf(np.x, s, fmaf(np.y, l * r, fmaf(np.z, __sinf(s), np.w)));
    }
    float u[2];
#pragma unroll
    for (int k = 0; k < 2; k++) {
        float4 np = snode[4 + k];
        float l = g[2 * k], r = g[2 * k + 1];
        float s = l + r;
        u[k] = fmaf(np.x, s, fmaf(np.y, l * r, fmaf(np.z, __sinf(s), np.w)));
    }
    {
        float4 np = snode[6];
        float l = u[0], r = u[1];
        float s = l + r;
        out[row] = fmaf(np.x, s, fmaf(np.y, l * r, fmaf(np.z, __sinf(s), np.w)));
    }
}

extern "C" void kernel_launch(void* const* d_in, const int* in_sizes, int n_in,
                              void* d_out, int out_size)
{
    const float* x      = (const float*)d_in[0];
    const float* W_leaf = (const float*)d_in[1];
    const float* b_leaf = (const float*)d_in[2];
    const float* w0     = (const float*)d_in[3];
    const float* w1     = (const float*)d_in[4];
    const float* w2     = (const float*)d_in[5];
    const float* b0     = (const float*)d_in[6];
    const float* b1     = (const float*)d_in[7];
    const float* b2     = (const float*)d_in[8];
    const float* om0    = (const float*)d_in[9];
    const float* om1    = (const float*)d_in[10];
    const float* om2    = (const float*)d_in[11];

    int n = in_sizes[0] / 16;

    // single D2D memcpy node: raw W_leaf straight into constant memory
    cudaMemcpyToSymbolAsync(cW, W_leaf, 128 * sizeof(float), 0,
                            cudaMemcpyDeviceToDevice);

    int blocks = (n + BLOCK - 1) / BLOCK;
    tree_rnn_kernel<<<blocks, BLOCK>>>(
        reinterpret_cast<const float4*>(x), (float*)d_out, n,
        b_leaf, w0, w1, w2, b0, b1, b2, om0, om1, om2);
}

// round 8
// speedup vs baseline: 1.1292x; 1.1281x over previous
#include <cuda_runtime.h>
#include <cstdint>

#define BLOCK 256

// ---------------------------------------------------------------------------
// BinaryTreeRNN: out[i] = tree_combine( x[i,0:16] @ W_leaf^T + b_leaf )
// 2 graph nodes:
//   (1) D2D memcpy of raw W_leaf into __constant__ (constant port for the
//       matvec weights -- even/odd-k accumulator packing needs no interleave).
//   (2) main kernel. Per-block param fold is placed AFTER the tile LDG/STS
//       issue and uses __expf/__fdividef, so it hides entirely under the
//       in-flight global loads instead of delaying them (the R7 mistake).
// ---------------------------------------------------------------------------

__constant__ __align__(16) float cW[128];   // W_leaf, raw row-major [8][16]

// ---- packed fp32x2 helpers (sm_103a) --------------------------------------

__device__ __forceinline__ unsigned long long fma2(unsigned long long a,
                                                   unsigned long long b,
                                                   unsigned long long c)
{
    unsigned long long d;
    asm("fma.rn.f32x2 %0, %1, %2, %3;" : "=l"(d) : "l"(a), "l"(b), "l"(c));
    return d;
}

__device__ __forceinline__ void unpack2(unsigned long long v, float& lo, float& hi)
{
    asm("mov.b64 {%0, %1}, %2;" : "=f"(lo), "=f"(hi) : "l"(v));
}

// ---- main kernel -----------------------------------------------------------

__global__ void __launch_bounds__(BLOCK)
tree_rnn_kernel(const float4* __restrict__ x4, float* __restrict__ out, int n,
                const float* __restrict__ bl,
                const float* __restrict__ w0,
                const float* __restrict__ w1,
                const float* __restrict__ w2,
                const float* __restrict__ b0,
                const float* __restrict__ b1,
                const float* __restrict__ b2,
                const float* __restrict__ om0,
                const float* __restrict__ om1,
                const float* __restrict__ om2)
{
    __shared__ float4 tile[BLOCK * 4];   // 256 rows x 16 floats, XOR-swizzled
    __shared__ float4 snode[7];          // (A, M, C, b) per tree node
    __shared__ float4 sbias[2];          // b_leaf as 2 float4

    const int t = threadIdx.x;

    // ---- Phase B FIRST: coalesced tile load, XOR-swizzled store -----------
    // (issues the big LDGs immediately; the param fold below overlaps them)
    const int n4 = n * 4;
    const int base4 = blockIdx.x * (BLOCK * 4);
#pragma unroll
    for (int j = 0; j < 4; j++) {
        int li = j * BLOCK + t;
        int g4 = base4 + li;
        float4 v;
        if (g4 < n4) v = x4[g4];
        else         v = make_float4(0.f, 0.f, 0.f, 0.f);
        int r = li >> 2;
        int q = li & 3;
        tile[(r << 2) + (q ^ ((r >> 1) & 3))] = v;
    }

    // ---- Phase A: fold tiny params into shared (hidden under Phase B) -----
    if (t < 7) {
        int i = t;   // 0-3: level2, 4-5: level1, 6: level0
        const float* om;
        float w, b;
        if (i < 4)      { om = om2 + 4 * i;       w = w2[i];     b = b2[i]; }
        else if (i < 6) { om = om1 + 4 * (i - 4); w = w1[i - 4]; b = b1[i - 4]; }
        else            { om = om0;               w = w0[0];     b = b0[0]; }
        float e0 = __expf(om[0]);
        float e1 = __expf(om[1]);
        float e2 = __expf(om[2]);
        float e3 = __expf(om[3]);
        float inv = __fdividef(w, e0 + e1 + e2 + e3);   // fold w into coeffs
        snode[i] = make_float4((e0 + e3) * inv, e1 * inv, e2 * inv, b);
    } else if (t < 9) {
        sbias[t - 7] = reinterpret_cast<const float4*>(bl)[t - 7];
    }
    __syncthreads();

    const int row = blockIdx.x * BLOCK + t;
    if (row >= n) return;

    // gather own row as x-pairs: float4 slot == ulonglong2{(x0,x1),(x2,x3)}
    const ulonglong2* tb = reinterpret_cast<const ulonglong2*>(tile);
    const int swz = (t >> 1) & 3;
    ulonglong2 xq0 = tb[(t << 2) + (0 ^ swz)];
    ulonglong2 xq1 = tb[(t << 2) + (1 ^ swz)];
    ulonglong2 xq2 = tb[(t << 2) + (2 ^ swz)];
    ulonglong2 xq3 = tb[(t << 2) + (3 ^ swz)];

    float4 bia0 = sbias[0];
    float4 bia1 = sbias[1];
    const float bj[8] = { bia0.x, bia0.y, bia0.z, bia0.w,
                          bia1.x, bia1.y, bia1.z, bia1.w };

    // leaf matvec: acc2[j] = ((even-k partial), (odd-k partial)), W from the
    // constant port in its natural layout (cw[j*4+c] = W[j][4c..4c+3]).
    const ulonglong2* cw = reinterpret_cast<const ulonglong2*>(cW);
    float h[8];
#pragma unroll
    for (int j = 0; j < 8; j++) {
        unsigned long long acc = 0ULL;   // (0.0f, 0.0f)
        ulonglong2 w0q = cw[j * 4 + 0];
        acc = fma2(w0q.x, xq0.x, acc);
        acc = fma2(w0q.y, xq0.y, acc);
        ulonglong2 w1q = cw[j * 4 + 1];
        acc = fma2(w1q.x, xq1.x, acc);
        acc = fma2(w1q.y, xq1.y, acc);
        ulonglong2 w2q = cw[j * 4 + 2];
        acc = fma2(w2q.x, xq2.x, acc);
        acc = fma2(w2q.y, xq2.y, acc);
        ulonglong2 w3q = cw[j * 4 + 3];
        acc = fma2(w3q.x, xq3.x, acc);
        acc = fma2(w3q.y, xq3.y, acc);
        float lo, hi;
        unpack2(acc, lo, hi);
        h[j] = lo + hi + bj[j];
    }

    // tree combine: val = A*s + M*(l*r) + C*sin(s) + b
    float g[4];
#pragma unroll
    for (int k = 0; k < 4; k++) {
        float4 np = snode[k];
        float l = h[2 * k], r = h[2 * k + 1];
        float s = l + r;
        g[k] = fmaf(np.x, s, fmaf(np.y, l * r, fmaf(np.z, __sinf(s), np.w)));
    }
    float u[2];
#pragma unroll
    for (int k = 0; k < 2; k++) {
        float4 np = snode[4 + k];
        float l = g[2 * k], r = g[2 * k + 1];
        float s = l + r;
        u[k] = fmaf(np.x, s, fmaf(np.y, l * r, fmaf(np.z, __sinf(s), np.w)));
    }
    {
        float4 np = snode[6];
        float l = u[0], r = u[1];
        float s = l + r;
        out[row] = fmaf(np.x, s, fmaf(np.y, l * r, fmaf(np.z, __sinf(s), np.w)));
    }
}

extern "C" void kernel_launch(void* const* d_in, const int* in_sizes, int n_in,
                              void* d_out, int out_size)
{
    const float* x      = (const float*)d_in[0];
    const float* W_leaf = (const float*)d_in[1];
    const float* b_leaf = (const float*)d_in[2];
    const float* w0     = (const float*)d_in[3];
    const float* w1     = (const float*)d_in[4];
    const float* w2     = (const float*)d_in[5];
    const float* b0     = (const float*)d_in[6];
    const float* b1     = (const float*)d_in[7];
    const float* b2     = (const float*)d_in[8];
    const float* om0    = (const float*)d_in[9];
    const float* om1    = (const float*)d_in[10];
    const float* om2    = (const float*)d_in[11];

    int n = in_sizes[0] / 16;

    // single D2D memcpy node: raw W_leaf straight into constant memory
    cudaMemcpyToSymbolAsync(cW, W_leaf, 128 * sizeof(float), 0,
                            cudaMemcpyDeviceToDevice);

    int blocks = (n + BLOCK - 1) / BLOCK;
    tree_rnn_kernel<<<blocks, BLOCK>>>(
        reinterpret_cast<const float4*>(x), (float*)d_out, n,
        b_leaf, w0, w1, w2, b0, b1, b2, om0, om1, om2);
}